// round 13
// baseline (speedup 1.0000x reference)
#include <cuda_runtime.h>
#include <math.h>

#define BB 8
#define SS 256
#define NTT 50
#define EE 64

#define P1_BLOCKS (BB * 64)          // 512: 4 balanced rows each
#define P2_BLOCKS (BB * NTT)         // 400: one (b,k) each
#define GRID (P1_BLOCKS + P2_BLOCKS) // 912

__device__ unsigned g_count = 0;              // reset by last block each call
__device__ double g_ll_part[P1_BLOCKS];
__device__ float  g_int_part[P2_BLOCKS];

__device__ __forceinline__ float ex2f(float x) {
    float y;
    asm("ex2.approx.ftz.f32 %0, %1;" : "=f"(y) : "f"(x));
    return y;
}

__device__ __forceinline__ float softplus_f(float x) {
    return fmaxf(x, 0.0f) + log1pf(__expf(-fabsf(x)));
}

__device__ __forceinline__ float read_T(const void* p) {
    int v = *(const int*)p;
    if (v > 0 && v < (1 << 26)) return (float)v;   // int32 / low half of int64
    return *(const float*)p;                        // float32 fallback
}

#define LOG2E 1.4426950408889634f

__global__ __launch_bounds__(256, 6) void body_k(
        const float* __restrict__ times, const int* __restrict__ types,
        const float* __restrict__ emb, const float* __restrict__ a,
        const float* __restrict__ Amat, const float* __restrict__ Pmat,
        const void* __restrict__ Tp, float* __restrict__ out) {
    // s_ap4[u*32 + ep] = { A'(2ep), P'(2ep), A'(2ep+1), P'(2ep+1) } for type-row u
    //   A' = e_u * A[u,ty,:],  P' = -LOG2E * e_row * e_u * P[u,ty,:]
    __shared__ __align__(16) float4 s_ap4[NTT * EE / 2];
    __shared__ __align__(16) float2 s_tj[SS];     // { time, int_as_float(type*EE) }
    __shared__ __align__(16) float2 s_part2[256];
    __shared__ float s_red[8];
    __shared__ int   s_last;

    const int tid = threadIdx.x;
    const int ep = tid & 31;        // e-pair index: covers e = 2ep, 2ep+1
    const int slice = tid >> 5;     // 8 j/i-slices
    const int lane = tid & 31;
    const int w = tid >> 5;

    const float4* __restrict__ emb4 = (const float4*)emb;
    const float2* __restrict__ emb2 = (const float2*)emb;
    const float2* __restrict__ a2p = (const float2*)a;
    const float4* __restrict__ A4 = (const float4*)Amat;
    const float4* __restrict__ P4 = (const float4*)Pmat;

    if (blockIdx.x < P1_BLOCKS) {
        // ---------------- part 1: log-likelihood ----------------
        const int b = blockIdx.x >> 6;
        const int grp = blockIdx.x & 63;

        for (int j = tid; j < SS; j += 256) {
            float2 v;
            v.x = times[b * SS + j];
            v.y = __int_as_float(types[b * SS + j] * EE);
            s_tj[j] = v;
        }
        __syncthreads();

        double ll_acc = 0.0;
        const int rows[4] = {2 * grp, 2 * grp + 1, 255 - 2 * grp, 254 - 2 * grp};

        #pragma unroll
        for (int r = 0; r < 4; r++) {
            const int i = rows[r];
            const float2 tji = s_tj[i];
            const float ti = tji.x;
            const int tyio = __float_as_int(tji.y);
            const int tyi = tyio >> 6;

            for (int idx4 = tid; idx4 < NTT * EE / 4; idx4 += 256) {
                const int u = idx4 >> 4;           // EE/4 = 16
                const int rm = idx4 & 15;
                const int g4 = (u * NTT + tyi) * 16 + rm;
                const float4 ev = __ldg(&emb4[idx4]);
                const float4 ki = __ldg(&emb4[tyi * 16 + rm]);
                const float4 av = __ldg(&A4[g4]);
                const float4 pv = __ldg(&P4[g4]);
                float4 lo, hi;
                lo.x = ev.x * av.x; lo.y = -LOG2E * ki.x * ev.x * pv.x;
                lo.z = ev.y * av.y; lo.w = -LOG2E * ki.y * ev.y * pv.y;
                hi.x = ev.z * av.z; hi.y = -LOG2E * ki.z * ev.z * pv.z;
                hi.z = ev.w * av.w; hi.w = -LOG2E * ki.w * ev.w * pv.w;
                s_ap4[2 * idx4] = lo;
                s_ap4[2 * idx4 + 1] = hi;
            }
            __syncthreads();

            float m0x = 0.0f, m0y = 0.0f, m1x = 0.0f, m1y = 0.0f;
            #pragma unroll 4
            for (int j = slice; j < i; j += 16) {
                const float2 tj = s_tj[j];
                const float4 ap = s_ap4[(__float_as_int(tj.y) >> 1) + ep];
                const float dt = ti - tj.x;
                m0x = fmaf(ap.x, ex2f(ap.y * dt), m0x);
                m0y = fmaf(ap.z, ex2f(ap.w * dt), m0y);
                const int j2 = j + 8;
                if (j2 < i) {
                    const float2 tj2 = s_tj[j2];
                    const float4 ap2 = s_ap4[(__float_as_int(tj2.y) >> 1) + ep];
                    const float dt2 = ti - tj2.x;
                    m1x = fmaf(ap2.x, ex2f(ap2.y * dt2), m1x);
                    m1y = fmaf(ap2.z, ex2f(ap2.w * dt2), m1y);
                }
            }
            float2 mm; mm.x = m0x + m1x; mm.y = m0y + m1y;
            s_part2[tid] = mm;
            __syncthreads();

            if (tid < 32) {
                float2 m = s_part2[ep];
                #pragma unroll
                for (int s = 1; s < 8; s++) {
                    const float2 v = s_part2[s * 32 + ep];
                    m.x += v.x; m.y += v.y;
                }
                const float2 ei2 = __ldg(&emb2[(tyio >> 1) + ep]);
                const float2 av2 = __ldg(&a2p[(tyio >> 1) + ep]);
                const float x0 = fmaf(ei2.x, av2.x, ei2.x * m.x);
                const float x1 = fmaf(ei2.y, av2.y, ei2.y * m.y);
                float sp = softplus_f(x0) + softplus_f(x1);
                #pragma unroll
                for (int off = 16; off > 0; off >>= 1)
                    sp += __shfl_xor_sync(0xffffffffu, sp, off);
                if (lane == 0) s_red[0] = sp;
            }
            __syncthreads();

            if (tid == 0 && ti >= 0.0f)
                ll_acc += (double)logf(s_red[0] + 1e-16f);
        }
        if (tid == 0) g_ll_part[blockIdx.x] = ll_acc;
    } else {
        // ---------------- part 2: intensity at T ----------------
        const int idx2 = blockIdx.x - P1_BLOCKS;
        const int b = idx2 / NTT;
        const int k = idx2 - b * NTT;

        for (int j = tid; j < SS; j += 256) {
            float2 v;
            v.x = times[b * SS + j];
            v.y = __int_as_float(types[b * SS + j] * EE);
            s_tj[j] = v;
        }
        for (int idx4 = tid; idx4 < NTT * EE / 4; idx4 += 256) {
            const int u = idx4 >> 4;
            const int rm = idx4 & 15;
            const int g4 = (u * NTT + k) * 16 + rm;
            const float4 ev = __ldg(&emb4[idx4]);
            const float4 ki = __ldg(&emb4[k * 16 + rm]);
            const float4 av = __ldg(&A4[g4]);
            const float4 pv = __ldg(&P4[g4]);
            float4 lo, hi;
            lo.x = ev.x * av.x; lo.y = -LOG2E * ki.x * ev.x * pv.x;
            lo.z = ev.y * av.y; lo.w = -LOG2E * ki.y * ev.y * pv.y;
            hi.x = ev.z * av.z; hi.y = -LOG2E * ki.z * ev.z * pv.z;
            hi.z = ev.w * av.w; hi.w = -LOG2E * ki.w * ev.w * pv.w;
            s_ap4[2 * idx4] = lo;
            s_ap4[2 * idx4 + 1] = hi;
        }
        __syncthreads();

        const float Tf = read_T(Tp);

        float m0x = 0.0f, m0y = 0.0f, m1x = 0.0f, m1y = 0.0f;
        #pragma unroll 4
        for (int i = slice; i < SS; i += 16) {
            const float2 tj = s_tj[i];
            if (tj.x >= 0.0f) {
                const float4 ap = s_ap4[(__float_as_int(tj.y) >> 1) + ep];
                const float dt = Tf - tj.x;
                m0x = fmaf(ap.x, ex2f(ap.y * dt), m0x);
                m0y = fmaf(ap.z, ex2f(ap.w * dt), m0y);
            }
            const float2 tj2 = s_tj[i + 8];
            if (tj2.x >= 0.0f) {
                const float4 ap2 = s_ap4[(__float_as_int(tj2.y) >> 1) + ep];
                const float dt2 = Tf - tj2.x;
                m1x = fmaf(ap2.x, ex2f(ap2.y * dt2), m1x);
                m1y = fmaf(ap2.z, ex2f(ap2.w * dt2), m1y);
            }
        }
        float2 mm; mm.x = m0x + m1x; mm.y = m0y + m1y;
        s_part2[tid] = mm;
        __syncthreads();

        if (tid < 32) {
            float2 m = s_part2[ep];
            #pragma unroll
            for (int s = 1; s < 8; s++) {
                const float2 v = s_part2[s * 32 + ep];
                m.x += v.x; m.y += v.y;
            }
            const float2 ek2 = __ldg(&emb2[k * 32 + ep]);
            const float2 av2 = __ldg(&a2p[k * 32 + ep]);
            const float x0 = fmaf(ek2.x, av2.x, ek2.x * m.x);
            const float x1 = fmaf(ek2.y, av2.y, ek2.y * m.y);
            float sp = softplus_f(x0) + softplus_f(x1);
            #pragma unroll
            for (int off = 16; off > 0; off >>= 1)
                sp += __shfl_xor_sync(0xffffffffu, sp, off);
            if (lane == 0) s_red[0] = sp;
        }
        __syncthreads();

        if (tid == 0) g_int_part[idx2] = s_red[0];
    }

    // ---------------- last block finishes ----------------
    if (tid == 0) {
        __threadfence();
        unsigned ticket = atomicAdd(&g_count, 1u);
        s_last = (ticket == GRID - 1);
    }
    __syncthreads();
    if (!s_last) return;

    // base_sum partials (deterministic tree)
    {
        float ps = 0.0f;
        for (int idx = tid; idx < NTT * EE; idx += 256)
            ps += softplus_f(emb[idx] * a[idx]);
        #pragma unroll
        for (int off = 16; off > 0; off >>= 1)
            ps += __shfl_xor_sync(0xffffffffu, ps, off);
        if (lane == 0) s_red[w] = ps;
    }

    // ll sum: 512 doubles
    __shared__ double s_dll[8];
    {
        double d = g_ll_part[tid] + g_ll_part[tid + 256];
        #pragma unroll
        for (int off = 16; off > 0; off >>= 1)
            d += __shfl_xor_sync(0xffffffffu, d, off);
        if (lane == 0) s_dll[w] = d;
    }

    // per-batch intensity-at-T sum + first/last/any scan (warp per batch)
    __shared__ float s_int[BB], s_first[BB], s_last_t[BB];
    __shared__ int s_any[BB];
    {
        float iv = 0.0f;
        if (lane < NTT) iv += g_int_part[w * NTT + lane];
        if (lane + 32 < NTT) iv += g_int_part[w * NTT + lane + 32];
        float mn = 1e30f, mx = -1e30f;
        int any = 0;
        #pragma unroll
        for (int mloop = 0; mloop < SS / 32; mloop++) {
            float t = times[w * SS + lane + 32 * mloop];
            if (t >= 0.0f) { any = 1; mn = fminf(mn, t); mx = fmaxf(mx, t); }
        }
        #pragma unroll
        for (int off = 16; off > 0; off >>= 1) {
            iv += __shfl_xor_sync(0xffffffffu, iv, off);
            mn = fminf(mn, __shfl_xor_sync(0xffffffffu, mn, off));
            mx = fmaxf(mx, __shfl_xor_sync(0xffffffffu, mx, off));
            any |= __shfl_xor_sync(0xffffffffu, any, off);
        }
        if (lane == 0) {
            s_int[w] = iv;
            s_any[w] = any;
            s_first[w] = any ? mn : 0.0f;
            s_last_t[w] = any ? mx : 0.0f;
        }
    }
    __syncthreads();

    if (tid == 0) {
        float base_sum = 0.0f;
        double ll = 0.0;
        #pragma unroll
        for (int ww = 0; ww < 8; ww++) { base_sum += s_red[ww]; ll += s_dll[ww]; }
        const float Tf = read_T(Tp);
        double integral = 0.0;
        for (int b = 0; b < BB; b++) {
            float ib;
            if (s_any[b]) ib = s_int[b] * (Tf - s_last_t[b]) + base_sum * s_first[b];
            else          ib = base_sum * Tf;
            integral += (double)ib;
        }
        out[0] = (float)(-(ll - integral));
        g_count = 0;   // reset for next graph replay (deterministic)
    }
}

extern "C" void kernel_launch(void* const* d_in, const int* in_sizes, int n_in,
                              void* d_out, int out_size) {
    const float* times = (const float*)d_in[0];
    const int*   types = (const int*)d_in[1];
    const void*  Tp    = d_in[2];
    const float* emb   = (const float*)d_in[3];
    const float* a     = (const float*)d_in[4];
    const float* Amat  = (const float*)d_in[5];
    const float* Pmat  = (const float*)d_in[6];
    float* out = (float*)d_out;

    body_k<<<GRID, 256>>>(times, types, emb, a, Amat, Pmat, Tp, out);
}